// round 2
// baseline (speedup 1.0000x reference)
#include <cuda_runtime.h>
#include <math.h>

// Problem constants (from reference)
#define NPROJS 128
#define L_DIM  1024
#define S_DIM  256
#define SPACING 4.7952f
#define MU0     0.013f

// Scratch (no allocation allowed in kernel_launch)
__device__ float g_partials[L_DIM];
__device__ unsigned int g_done_count = 0;   // must be 0 at every kernel entry

// One block per row l. 256 threads, thread t handles element t of both slices.
// Last block to finish performs the deterministic final reduction.
__global__ void __launch_bounds__(S_DIM) edcc_fused_kernel(
    const float* __restrict__ projs, float sigma, float* __restrict__ out)
{
    const int l = blockIdx.x;
    const int t = threadIdx.x;

    // Base pointers for the two used projection slices (i=127, j=29)
    const float* __restrict__ pi = projs + (size_t)127 * L_DIM * S_DIM + (size_t)l * S_DIM;
    const float* __restrict__ pj = projs + (size_t)29  * L_DIM * S_DIM + (size_t)l * S_DIM;

    // s grid: linspace((-S*sp+sp)/2, (S*sp-sp)/2, S) -> step == SPACING
    const float s_start = (-(float)S_DIM * SPACING + SPACING) * 0.5f;
    const float s = s_start + (float)t * SPACING;
    const float w = expf(sigma * s * SPACING);

    float vi = pi[t] * w;
    float vj = pj[t] * w;

    // Block reduction (8 warps), deterministic tree order
    __shared__ float sh_i[8];
    __shared__ float sh_j[8];
    __shared__ bool  sh_last;
    const int lane = t & 31;
    const int warp = t >> 5;
    #pragma unroll
    for (int off = 16; off > 0; off >>= 1) {
        vi += __shfl_down_sync(0xFFFFFFFFu, vi, off);
        vj += __shfl_down_sync(0xFFFFFFFFu, vj, off);
    }
    if (lane == 0) { sh_i[warp] = vi; sh_j[warp] = vj; }
    __syncthreads();

    if (t == 0) {
        float Pi = 0.0f, Pj = 0.0f;
        #pragma unroll
        for (int k = 0; k < 8; k++) { Pi += sh_i[k]; Pj += sh_j[k]; }
        float den = Pi + Pj;
        float term = (den != 0.0f)
                   ? (2.0f / (float)NPROJS) * fabsf(Pi - Pj) / den
                   : 0.0f;
        g_partials[l] = term;
        __threadfence();
        unsigned int old = atomicAdd(&g_done_count, 1u);
        sh_last = (old == (unsigned int)(gridDim.x - 1));
    }
    __syncthreads();

    // Last block performs the final reduction in a fixed, deterministic order.
    if (sh_last) {
        float acc = 0.0f;
        #pragma unroll
        for (int k = 0; k < L_DIM / S_DIM; k++)
            acc += g_partials[t + k * S_DIM];

        __shared__ float sh[8];
        #pragma unroll
        for (int off = 16; off > 0; off >>= 1)
            acc += __shfl_down_sync(0xFFFFFFFFu, acc, off);
        if (lane == 0) sh[warp] = acc;
        __syncthreads();

        if (t == 0) {
            float total = 0.0f;
            #pragma unroll
            for (int k = 0; k < 8; k++) total += sh[k];
            out[0] = total;         // mean over batch B=1 -> identity
            g_done_count = 0;       // re-arm for next graph replay
        }
    }
}

extern "C" void kernel_launch(void* const* d_in, const int* in_sizes, int n_in,
                              void* d_out, int out_size)
{
    const float* projs = (const float*)d_in[0];
    float* out = (float*)d_out;

    // sigma = MU0 * tan((theta[127] - theta[29]) / 2), theta_k = 2*pi*k/128
    const double two_pi = 6.283185307179586;
    const double th_i = two_pi * 127.0 / 128.0;
    const double th_j = two_pi * 29.0 / 128.0;
    const float sigma = (float)((double)MU0 * tan((th_i - th_j) * 0.5));

    edcc_fused_kernel<<<L_DIM, S_DIM>>>(projs, sigma, out);
}

// round 3
// speedup vs baseline: 1.3413x; 1.3413x over previous
#include <cuda_runtime.h>
#include <math.h>

// Problem constants (from reference)
#define NPROJS 128
#define L_DIM  1024
#define S_DIM  256
#define SPACING 4.7952f
#define MU0     0.013f

#define NBLOCKS 128            // one wave on 148 SMs
#define ROWS_PER_BLOCK 8       // one warp per row

// Scratch (no allocation allowed in kernel_launch)
__device__ float g_block_partials[NBLOCKS];
__device__ unsigned int g_done_count = 0;   // must be 0 at every kernel entry

__global__ void __launch_bounds__(256) edcc_fused_kernel(
    const float* __restrict__ projs, float sigma, float* __restrict__ out)
{
    const int lane = threadIdx.x & 31;
    const int warp = threadIdx.x >> 5;      // 0..7 -> row within block
    const int l = blockIdx.x * ROWS_PER_BLOCK + warp;

    // Two used projection slices (i=127, j=29); one warp handles one row l.
    const float4* __restrict__ pi = (const float4*)(projs
        + (size_t)127 * L_DIM * S_DIM + (size_t)l * S_DIM);
    const float4* __restrict__ pj = (const float4*)(projs
        + (size_t)29  * L_DIM * S_DIM + (size_t)l * S_DIM);

    // Weight: w(e) = exp(sigma * s(e) * SPACING), s(e) = s_start + e*SPACING
    const float s_start = (-(float)S_DIM * SPACING + SPACING) * 0.5f;
    const float c1 = sigma * SPACING;            // multiply by s(e)
    const float base = c1 * s_start;             // arg(e) = base + e * (c1*SPACING)
    const float step = c1 * SPACING;

    float vi = 0.0f, vj = 0.0f;
    #pragma unroll
    for (int r = 0; r < 2; r++) {
        const int f = lane + r * 32;             // float4 index within row (0..63)
        const float4 a = pi[f];
        const float4 b = pj[f];
        const int e = f * 4;
        const float w0 = expf(base + (float)(e + 0) * step);
        const float w1 = expf(base + (float)(e + 1) * step);
        const float w2 = expf(base + (float)(e + 2) * step);
        const float w3 = expf(base + (float)(e + 3) * step);
        vi += a.x * w0 + a.y * w1 + a.z * w2 + a.w * w3;
        vj += b.x * w0 + b.y * w1 + b.z * w2 + b.w * w3;
    }

    // Warp reduction -> P_i, P_j for this row
    #pragma unroll
    for (int off = 16; off > 0; off >>= 1) {
        vi += __shfl_down_sync(0xFFFFFFFFu, vi, off);
        vj += __shfl_down_sync(0xFFFFFFFFu, vj, off);
    }

    __shared__ float sh_terms[ROWS_PER_BLOCK];
    __shared__ bool  sh_last;
    if (lane == 0) {
        const float den = vi + vj;
        sh_terms[warp] = (den != 0.0f)
                       ? (2.0f / (float)NPROJS) * fabsf(vi - vj) / den
                       : 0.0f;
    }
    __syncthreads();

    if (threadIdx.x == 0) {
        float bsum = 0.0f;
        #pragma unroll
        for (int k = 0; k < ROWS_PER_BLOCK; k++) bsum += sh_terms[k];
        g_block_partials[blockIdx.x] = bsum;
        __threadfence();
        const unsigned int old = atomicAdd(&g_done_count, 1u);
        sh_last = (old == (unsigned int)(NBLOCKS - 1));
    }
    __syncthreads();

    // Last block: deterministic fixed-order reduction of 128 partials.
    if (sh_last) {
        float acc = (threadIdx.x < NBLOCKS) ? g_block_partials[threadIdx.x] : 0.0f;
        __shared__ float sh[8];
        #pragma unroll
        for (int off = 16; off > 0; off >>= 1)
            acc += __shfl_down_sync(0xFFFFFFFFu, acc, off);
        if (lane == 0) sh[warp] = acc;
        __syncthreads();
        if (threadIdx.x == 0) {
            float total = 0.0f;
            #pragma unroll
            for (int k = 0; k < 4; k++) total += sh[k];  // warps 4..7 contributed zeros
            total += sh[4] + sh[5] + sh[6] + sh[7];
            out[0] = total;         // mean over batch B=1 -> identity
            g_done_count = 0;       // re-arm for next graph replay
        }
    }
}

extern "C" void kernel_launch(void* const* d_in, const int* in_sizes, int n_in,
                              void* d_out, int out_size)
{
    const float* projs = (const float*)d_in[0];
    float* out = (float*)d_out;

    // sigma = MU0 * tan((theta[127] - theta[29]) / 2), theta_k = 2*pi*k/128
    const double two_pi = 6.283185307179586;
    const double th_i = two_pi * 127.0 / 128.0;
    const double th_j = two_pi * 29.0 / 128.0;
    const float sigma = (float)((double)MU0 * tan((th_i - th_j) * 0.5));

    edcc_fused_kernel<<<NBLOCKS, 256>>>(projs, sigma, out);
}

// round 4
// speedup vs baseline: 1.3478x; 1.0048x over previous
#include <cuda_runtime.h>
#include <math.h>

// Problem constants (from reference)
#define NPROJS 128
#define L_DIM  1024
#define S_DIM  256
#define SPACING 4.7952f
#define MU0     0.013f

#define NBLOCKS 128            // one wave
#define ROWS_PER_BLOCK 8       // one warp per row, 256 threads/block

// Packed accumulator: bits [0:56) fixed-point sum (scale 2^40),
//                     bits [56:64) arrival count. Zero at load; last
// arrival resets it for the next graph replay.
__device__ unsigned long long g_acc = 0ULL;

#define FIX_SCALE   1099511627776.0f      /* 2^40 */
#define FIX_INV     (1.0 / 1099511627776.0)
#define COUNT_ONE   (1ULL << 56)
#define SUM_MASK    ((1ULL << 56) - 1ULL)

__global__ void __launch_bounds__(256) edcc_fused_kernel(
    const float* __restrict__ projs, float sigma, float* __restrict__ out)
{
    const int lane = threadIdx.x & 31;
    const int warp = threadIdx.x >> 5;      // 0..7 -> row within block
    const int l = blockIdx.x * ROWS_PER_BLOCK + warp;

    // Two used projection slices (i=127, j=29); one warp handles row l.
    const float4* __restrict__ pi = (const float4*)(projs
        + (size_t)127 * L_DIM * S_DIM + (size_t)l * S_DIM);
    const float4* __restrict__ pj = (const float4*)(projs
        + (size_t)29  * L_DIM * S_DIM + (size_t)l * S_DIM);

    // Front-batch all 4 independent 16B loads (max MLP before any use)
    const float4 a0 = pi[lane];
    const float4 a1 = pi[lane + 32];
    const float4 b0 = pj[lane];
    const float4 b1 = pj[lane + 32];

    // Weight: w(e) = exp(sigma * s(e) * SPACING), s(e) = s_start + e*SPACING
    const float s_start = (-(float)S_DIM * SPACING + SPACING) * 0.5f;
    const float c1 = sigma * SPACING;
    const float base = c1 * s_start;
    const float step = c1 * SPACING;

    float vi, vj;
    {
        const int e0 = lane * 4;
        const float w0 = __expf(base + (float)(e0 + 0) * step);
        const float w1 = __expf(base + (float)(e0 + 1) * step);
        const float w2 = __expf(base + (float)(e0 + 2) * step);
        const float w3 = __expf(base + (float)(e0 + 3) * step);
        const int e1 = (lane + 32) * 4;
        const float u0 = __expf(base + (float)(e1 + 0) * step);
        const float u1 = __expf(base + (float)(e1 + 1) * step);
        const float u2 = __expf(base + (float)(e1 + 2) * step);
        const float u3 = __expf(base + (float)(e1 + 3) * step);

        vi = a0.x * w0 + a0.y * w1 + a0.z * w2 + a0.w * w3
           + a1.x * u0 + a1.y * u1 + a1.z * u2 + a1.w * u3;
        vj = b0.x * w0 + b0.y * w1 + b0.z * w2 + b0.w * w3
           + b1.x * u0 + b1.y * u1 + b1.z * u2 + b1.w * u3;
    }

    // Warp reduction -> P_i, P_j for this row
    #pragma unroll
    for (int off = 16; off > 0; off >>= 1) {
        vi += __shfl_down_sync(0xFFFFFFFFu, vi, off);
        vj += __shfl_down_sync(0xFFFFFFFFu, vj, off);
    }

    __shared__ float sh_terms[ROWS_PER_BLOCK];
    if (lane == 0) {
        const float den = vi + vj;
        sh_terms[warp] = (den != 0.0f)
                       ? (2.0f / (float)NPROJS) * fabsf(vi - vj) / den
                       : 0.0f;
    }
    __syncthreads();

    if (threadIdx.x == 0) {
        float bsum = 0.0f;
        #pragma unroll
        for (int k = 0; k < ROWS_PER_BLOCK; k++) bsum += sh_terms[k];

        // Fixed-point contribution + arrival count in ONE atomic.
        // Integer adds commute -> result is bitwise deterministic.
        const unsigned long long contrib =
            (unsigned long long)(bsum * FIX_SCALE) | COUNT_ONE;
        const unsigned long long old = atomicAdd(&g_acc, contrib);

        if ((old >> 56) == (unsigned long long)(NBLOCKS - 1)) {
            const unsigned long long total = (old + contrib) & SUM_MASK;
            out[0] = (float)((double)total * FIX_INV);  // mean over B=1 -> identity
            g_acc = 0ULL;   // re-arm for next graph replay (same-thread ordering)
        }
    }
}

extern "C" void kernel_launch(void* const* d_in, const int* in_sizes, int n_in,
                              void* d_out, int out_size)
{
    const float* projs = (const float*)d_in[0];
    float* out = (float*)d_out;

    // sigma = MU0 * tan((theta[127] - theta[29]) / 2), theta_k = 2*pi*k/128
    const double two_pi = 6.283185307179586;
    const double th_i = two_pi * 127.0 / 128.0;
    const double th_j = two_pi * 29.0 / 128.0;
    const float sigma = (float)((double)MU0 * tan((th_i - th_j) * 0.5));

    edcc_fused_kernel<<<NBLOCKS, 256>>>(projs, sigma, out);
}